// round 16
// baseline (speedup 1.0000x reference)
#include <cuda_runtime.h>
#include <cuda_bf16.h>
#include <math.h>
#include <stdint.h>

#define TT 512
#define DD 512
#define LOG2E 1.4426950408889634f

// ---------------------------------------------------------------------------
// Device-global scratch
// ---------------------------------------------------------------------------
__device__ float g_qp[2][1536 * 512];                    // gemm1 split-K partials
__device__ __align__(16) __nv_bfloat16 g_aohi[DD * TT];  // ao hi, [d][t]
__device__ __align__(16) __nv_bfloat16 g_aolo[DD * TT];  // ao lo residual
__device__ __align__(16) __nv_bfloat16 gAhi[1536 * 512]; // Wq,Wk,Wv stacked hi
__device__ __align__(16) __nv_bfloat16 gAlo[1536 * 512];
__device__ __align__(16) __nv_bfloat16 gBhi[512 * 512];  // x [t][k]
__device__ __align__(16) __nv_bfloat16 gBlo[512 * 512];
__device__ __align__(16) __nv_bfloat16 gWohi[512 * 512]; // Wo [o][d]
__device__ __align__(16) __nv_bfloat16 gWolo[512 * 512];

__device__ __forceinline__ uint32_t smem_u32(const void* p) {
    uint32_t a;
    asm("{ .reg .u64 t; cvta.to.shared.u64 t, %1; cvt.u32.u64 %0, t; }"
        : "=r"(a) : "l"(p));
    return a;
}
__device__ __forceinline__ void cp16(uint32_t dst, const void* src) {
    asm volatile("cp.async.ca.shared.global [%0], [%1], 16;"
                 :: "r"(dst), "l"(src) : "memory");
}
__device__ __forceinline__ float fast_ex2(float x) {
    float r;
    asm("ex2.approx.ftz.f32 %0, %1;" : "=f"(r) : "f"(x));
    return r;
}

// exp2 on the FMA pipe: magic-constant range reduction + deg-4 poly +
// exponent splice. Valid for |x| < ~60; rel err ~3e-5. No MUFU usage.
__device__ __forceinline__ float poly_ex2(float s) {
    const float t = s + 12582912.0f;              // round-to-nearest int
    const int   ni = __float_as_int(t) - 0x4B400000;
    const float n = t - 12582912.0f;
    const float f = s - n;                        // f in [-0.5, 0.5]
    float p = 0.0096181291f;                      // ~ln2^4/24
    p = fmaf(p, f, 0.0555041087f);                // ~ln2^3/6
    p = fmaf(p, f, 0.2402265069f);                // ~ln2^2/2
    p = fmaf(p, f, 0.6931471806f);                // ln2
    p = fmaf(p, f, 1.0f);
    return __int_as_float(__float_as_int(p) + (ni << 23));
}

// Blackwell packed f32x2 ops (PTX sm_100+ family, baseline)
#define MUL_F32X2(d, a, b) \
    asm("mul.rn.f32x2 %0, %1, %2;" : "=l"(d) : "l"(a), "l"(b))
#define ADD_F32X2_ACC(d, a) \
    asm("add.rn.f32x2 %0, %0, %1;" : "+l"(d) : "l"(a))
#define FMA_F32X2_ACC(d, a, b) \
    asm("fma.rn.f32x2 %0, %1, %2, %0;" : "+l"(d) : "l"(a), "l"(b))
#define PACK_F32X2(d, lo, hi) \
    asm("mov.b64 %0, {%1, %2};" : "=l"(d) : "f"(lo), "f"(hi))
#define UNPACK_F32X2(lo, hi, s) \
    asm("mov.b64 {%0, %1}, %2;" : "=f"(lo), "=f"(hi) : "l"(s))

#define MMA16816(c, a, b) \
    asm volatile( \
        "mma.sync.aligned.m16n8k16.row.col.f32.bf16.bf16.f32 " \
        "{%0,%1,%2,%3},{%4,%5,%6,%7},{%8,%9},{%0,%1,%2,%3};" \
        : "+f"((c)[0]), "+f"((c)[1]), "+f"((c)[2]), "+f"((c)[3]) \
        : "r"((a)[0]), "r"((a)[1]), "r"((a)[2]), "r"((a)[3]), \
          "r"((b)[0]), "r"((b)[1]))

#define LDMX4(r, a) \
    asm volatile( \
        "ldmatrix.sync.aligned.m8n8.x4.shared.b16 {%0,%1,%2,%3}, [%4];" \
        : "=r"((r)[0]), "=r"((r)[1]), "=r"((r)[2]), "=r"((r)[3]) : "r"(a))

#define LDMX4T(r, a) \
    asm volatile( \
        "ldmatrix.sync.aligned.m8n8.x4.trans.shared.b16 {%0,%1,%2,%3}, [%4];" \
        : "=r"((r)[0]), "=r"((r)[1]), "=r"((r)[2]), "=r"((r)[3]) : "r"(a))

// ---------------------------------------------------------------------------
// Split kernel: fp32 -> bf16 hi + bf16 lo(residual). (unchanged)
// ---------------------------------------------------------------------------
__global__ void __launch_bounds__(256) split_kernel(
        const float4* __restrict__ x,  const float4* __restrict__ Wq,
        const float4* __restrict__ Wk, const float4* __restrict__ Wv,
        const float4* __restrict__ Wo) {
    const int gid = blockIdx.x * 256 + threadIdx.x;   // 0..327679
    const int seg = gid >> 16;
    const int off = gid & 65535;

    const float4* src;
    __nv_bfloat16 *dh, *dl;
    switch (seg) {
        case 0: src = Wq; dh = gAhi;          dl = gAlo;          break;
        case 1: src = Wk; dh = gAhi + 262144; dl = gAlo + 262144; break;
        case 2: src = Wv; dh = gAhi + 524288; dl = gAlo + 524288; break;
        case 3: src = x;  dh = gBhi;          dl = gBlo;          break;
        default: src = Wo; dh = gWohi;         dl = gWolo;         break;
    }
    float4 v = src[off];
    __nv_bfloat16 h0 = __float2bfloat16(v.x), h1 = __float2bfloat16(v.y);
    __nv_bfloat16 h2 = __float2bfloat16(v.z), h3 = __float2bfloat16(v.w);
    __nv_bfloat16 l0 = __float2bfloat16(v.x - __bfloat162float(h0));
    __nv_bfloat16 l1 = __float2bfloat16(v.y - __bfloat162float(h1));
    __nv_bfloat16 l2 = __float2bfloat16(v.z - __bfloat162float(h2));
    __nv_bfloat16 l3 = __float2bfloat16(v.w - __bfloat162float(h3));
    __nv_bfloat162* oh = (__nv_bfloat162*)dh;
    __nv_bfloat162* ol = (__nv_bfloat162*)dl;
    __nv_bfloat162 a, b;
    a.x = h0; a.y = h1; b.x = h2; b.y = h3;
    oh[off * 2] = a; oh[off * 2 + 1] = b;
    a.x = l0; a.y = l1; b.x = l2; b.y = l3;
    ol[off * 2] = a; ol[off * 2 + 1] = b;
}

// ---------------------------------------------------------------------------
// GEMM1 (unchanged): 64x64 tile, split-K=2, 256 threads, 2-stage.
// ---------------------------------------------------------------------------
#define G1_MAT 9216                       // 64 rows * 144B
#define G1_CHUNK (4 * G1_MAT)             // 36864
#define GEMM1_SMEM (2 * G1_CHUNK)         // 73728
#define G2_CHUNK (2 * 5120 + 2 * 9216)    // 28672 (ATRANS A rows 80B)
#define GEMM2_SMEM (3 * G2_CHUNK)         // 86016 (3-stage, round-11 config)

__global__ void __launch_bounds__(256, 3) gemm1_kernel() {
    extern __shared__ char smem[];
    const uint32_t s0 = smem_u32(smem);
    const uint4* AH = (const uint4*)gAhi;
    const uint4* AL = (const uint4*)gAlo;
    const uint4* BH = (const uint4*)gBhi;
    const uint4* BL = (const uint4*)gBlo;

    const int tid = threadIdx.x;
    const int wid = tid >> 5, lane = tid & 31;
    const int g = lane >> 2, t4 = lane & 3;
    const int wm = (wid & 3) * 16;
    const int wn = (wid >> 2) * 32;
    const int m0 = blockIdx.x * 64, n0 = blockIdx.y * 64;
    const int kz = blockIdx.z;
    float* C = g_qp[kz];

    const int arow  = lane & 15;
    const int aksel = (lane >> 4) * 16;
    const int brow  = ((lane >> 4) & 1) * 8 + (lane & 7);
    const int bksel = ((lane >> 3) & 1) * 16;

    float accA[4][4] = {}, accB[4][4] = {};

    auto load_chunk = [&](int c, int st) {
        const uint32_t base = s0 + st * G1_CHUNK;
        const int kc = kz * 4 + c;
#pragma unroll
        for (int it = 0; it < 2; it++) {
            const int idx = it * 256 + tid;
            const int row = idx >> 3, c16 = idx & 7;
            const uint32_t so = row * 144 + c16 * 16;
            const size_t ga = (size_t)(m0 + row) * 64 + kc * 8 + c16;
            const size_t gb = (size_t)(n0 + row) * 64 + kc * 8 + c16;
            cp16(base + so,              AH + ga);
            cp16(base + G1_MAT + so,     AL + ga);
            cp16(base + 2 * G1_MAT + so, BH + gb);
            cp16(base + 3 * G1_MAT + so, BL + gb);
        }
        asm volatile("cp.async.commit_group;" ::: "memory");
    };

    load_chunk(0, 0);

    for (int c = 0; c < 4; c++) {
        if (c < 3) {
            load_chunk(c + 1, (c + 1) & 1);
            asm volatile("cp.async.wait_group 1;" ::: "memory");
        } else {
            asm volatile("cp.async.wait_group 0;" ::: "memory");
        }
        __syncthreads();

        const uint32_t sb = s0 + (c & 1) * G1_CHUNK;
#pragma unroll
        for (int ks = 0; ks < 4; ks++) {
            const int kO = ks * 32;
            uint32_t ah[4], al[4], bh[2][4], bl[2][4];
            {
                const uint32_t ad = sb + (wm + arow) * 144 + kO + aksel;
                LDMX4(ah, ad);
                LDMX4(al, ad + G1_MAT);
            }
#pragma unroll
            for (int nb = 0; nb < 2; nb++) {
                const uint32_t bd = sb + 2 * G1_MAT
                                  + (wn + nb * 16 + brow) * 144 + kO + bksel;
                LDMX4(bh[nb], bd);
                LDMX4(bl[nb], bd + G1_MAT);
            }
#pragma unroll
            for (int nb = 0; nb < 2; nb++)
#pragma unroll
                for (int j = 0; j < 2; j++) {
                    MMA16816(accA[nb * 2 + j], ah, &bh[nb][j * 2]);
                    MMA16816(accB[nb * 2 + j], ah, &bl[nb][j * 2]);
                    MMA16816(accB[nb * 2 + j], al, &bh[nb][j * 2]);
                }
        }
        __syncthreads();
    }

    const int r = m0 + wm + g;
#pragma unroll
    for (int q = 0; q < 4; q++) {
        const int nb = q >> 1, j = q & 1;
        const int col = n0 + wn + nb * 16 + j * 8 + 2 * t4;
        *(float2*)&C[(size_t)r * 512 + col] =
            make_float2(accA[q][0] + accB[q][0], accA[q][1] + accB[q][1]);
        *(float2*)&C[(size_t)(r + 8) * 512 + col] =
            make_float2(accA[q][2] + accB[q][2], accA[q][3] + accB[q][3]);
    }
}

// ---------------------------------------------------------------------------
// GEMM2: round-11 config restored (split-K=2, 3-stage, atomics) — measured
// 8.96us vs 9.7us for the split-K=4 2-stage variant.
// ---------------------------------------------------------------------------
__global__ void __launch_bounds__(256, 2) gemm2_kernel(float* __restrict__ y) {
    extern __shared__ char smem[];
    const uint32_t s0 = smem_u32(smem);
    const uint4* AH = (const uint4*)g_aohi;
    const uint4* AL = (const uint4*)g_aolo;
    const uint4* BH = (const uint4*)gWohi;
    const uint4* BL = (const uint4*)gWolo;

    constexpr int AROWB = 80, A_MAT = 64 * 80;
    constexpr int B_MAT = 9216;

    const int tid = threadIdx.x;
    const int wid = tid >> 5, lane = tid & 31;
    const int g = lane >> 2, t4 = lane & 3;
    const int wm = (wid & 1) * 16;
    const int wn = (wid >> 1) * 16;
    const int m0 = blockIdx.x * 32, n0 = blockIdx.y * 64;
    const int kc0 = blockIdx.z * 4;

    const int brow  = ((lane >> 4) & 1) * 8 + (lane & 7);
    const int bksel = ((lane >> 3) & 1) * 16;
    const int laneRow  = ((lane >> 4) & 1) * 8 + (lane & 7);
    const int laneMsel = ((lane >> 3) & 1) * 8;

    float accH[2][4] = {}, accM[2][4] = {}, accN[2][4] = {};

    auto load_chunk = [&](int kc, int st) {
        const uint32_t base = s0 + st * G2_CHUNK;
        {
            const int row = tid >> 2, c16 = tid & 3;
            const uint32_t so = row * AROWB + c16 * 16;
            const size_t ga = (size_t)(kc * 64 + row) * 64 + (m0 >> 3) + c16;
            cp16(base + so,         AH + ga);
            cp16(base + A_MAT + so, AL + ga);
        }
#pragma unroll
        for (int it = 0; it < 2; it++) {
            const int idx = it * 256 + tid;
            const int row = idx >> 3, c16 = idx & 7;
            const uint32_t so = row * 144 + c16 * 16;
            const size_t gb = (size_t)(n0 + row) * 64 + kc * 8 + c16;
            cp16(base + 2 * A_MAT + so,         BH + gb);
            cp16(base + 2 * A_MAT + B_MAT + so, BL + gb);
        }
        asm volatile("cp.async.commit_group;" ::: "memory");
    };

    load_chunk(kc0 + 0, 0);
    load_chunk(kc0 + 1, 1);

    for (int c = 0; c < 4; c++) {
        if (c + 2 < 4) {
            load_chunk(kc0 + c + 2, (c + 2) % 3);
            asm volatile("cp.async.wait_group 2;" ::: "memory");
        } else if (c + 1 < 4) {
            asm volatile("cp.async.wait_group 1;" ::: "memory");
        } else {
            asm volatile("cp.async.wait_group 0;" ::: "memory");
        }
        __syncthreads();

        const uint32_t sb = s0 + (c % 3) * G2_CHUNK;
#pragma unroll
        for (int ks = 0; ks < 4; ks++) {
            const int kO = ks * 32;
            uint32_t ah[4], al[4], bh[4], bl[4];
            {
                const uint32_t ad = sb + (ks * 16 + laneRow) * AROWB
                                  + (wm + laneMsel) * 2;
                LDMX4T(ah, ad);
                LDMX4T(al, ad + A_MAT);
            }
            {
                const uint32_t bd = sb + 2 * A_MAT + (wn + brow) * 144
                                  + kO + bksel;
                LDMX4(bh, bd);
                LDMX4(bl, bd + B_MAT);
            }
#pragma unroll
            for (int j = 0; j < 2; j++) {
                MMA16816(accH[j], ah, &bh[j * 2]);
                MMA16816(accM[j], ah, &bl[j * 2]);
                MMA16816(accN[j], al, &bh[j * 2]);
            }
        }
        __syncthreads();
    }

    const int r = m0 + wm + g;
#pragma unroll
    for (int j = 0; j < 2; j++) {
        const int col = n0 + wn + j * 8 + 2 * t4;
        atomicAdd(&y[(size_t)r * 512 + col],
                  accH[j][0] + accM[j][0] + accN[j][0]);
        atomicAdd(&y[(size_t)r * 512 + col + 1],
                  accH[j][1] + accM[j][1] + accN[j][1]);
        atomicAdd(&y[(size_t)(r + 8) * 512 + col],
                  accH[j][2] + accM[j][2] + accN[j][2]);
        atomicAdd(&y[(size_t)(r + 8) * 512 + col + 1],
                  accH[j][3] + accM[j][3] + accN[j][3]);
    }
}

// ---------------------------------------------------------------------------
// Attention: fused RoPE, 4-wide f32x2 loop; per group of 4, 3 exps on MUFU
// (ex2.approx.f32) and 1 on the FMA pipe (poly_ex2) to lift the MUFU floor.
// ---------------------------------------------------------------------------
__global__ void __launch_bounds__(256) attn_kernel(float* __restrict__ y) {
    const int c  = blockIdx.x;
    const int h  = c >> 6;
    const int ch = c & 63;
    const int fi = ch & 31;
    const int pc = ((h < 4) ? (h + 4) : (h - 4)) * 64 + ch;
    const float sgn = (h < 4) ? -1.0f : 1.0f;

    const float* q0  = g_qp[0] + (size_t)(0 * 512 + c)  * TT;
    const float* q1  = g_qp[1] + (size_t)(0 * 512 + c)  * TT;
    const float* qp0 = g_qp[0] + (size_t)(0 * 512 + pc) * TT;
    const float* qp1 = g_qp[1] + (size_t)(0 * 512 + pc) * TT;
    const float* k0  = g_qp[0] + (size_t)(1 * 512 + c)  * TT;
    const float* k1  = g_qp[1] + (size_t)(1 * 512 + c)  * TT;
    const float* kp0 = g_qp[0] + (size_t)(1 * 512 + pc) * TT;
    const float* kp1 = g_qp[1] + (size_t)(1 * 512 + pc) * TT;
    const float* v0  = g_qp[0] + (size_t)(2 * 512 + c)  * TT;
    const float* v1  = g_qp[1] + (size_t)(2 * 512 + c)  * TT;

    __shared__ __align__(16) float ks[512];  // rotated k, pre-scaled
    __shared__ __align__(16) float vs[512];
    __shared__ float cs[512];
    __shared__ float sn[512];
    __shared__ float s_invf;

    const int tid = threadIdx.x;
    *(float2*)&y[c * 512 + tid * 2] = make_float2(0.f, 0.f);

    if (tid == 0) s_invf = (float)pow(10000.0, -(double)(2 * fi) / 64.0);
    __syncthreads();
    const float invf = s_invf;

#pragma unroll
    for (int off = 0; off < 512; off += 256) {
        const int tt = tid + off;
        float sv, cv;
        sincosf((float)tt * invf, &sv, &cv);
        cs[tt] = cv;
        sn[tt] = sv;
        ks[tt] = ((k0[tt] + k1[tt]) * cv + sgn * (kp0[tt] + kp1[tt]) * sv)
               * (0.125f * LOG2E);
        vs[tt] = v0[tt] + v1[tt];
    }
    __syncthreads();

    const ulonglong2* k4 = (const ulonglong2*)ks;
    const ulonglong2* v4 = (const ulonglong2*)vs;

#pragma unroll
    for (int rep = 0; rep < 2; rep++) {
        const int i = rep ? (511 - tid) : tid;
        const float qr = (q0[i] + q1[i]) * cs[i]
                       + sgn * (qp0[i] + qp1[i]) * sn[i];
        unsigned long long qq;
        PACK_F32X2(qq, qr, qr);

        unsigned long long l2a = 0ull, l2b = 0ull;
        unsigned long long a2a = 0ull, a2b = 0ull;
        const int n4 = (i + 1) >> 2;
#pragma unroll 2
        for (int p = 0; p < n4; p++) {
            const ulonglong2 kk = k4[p];   // LDS.128 (4 k vals)
            const ulonglong2 vv = v4[p];   // LDS.128 (4 v vals)
            unsigned long long s01, s23;
            MUL_F32X2(s01, qq, kk.x);
            MUL_F32X2(s23, qq, kk.y);
            float sa, sb, sc, sd;
            UNPACK_F32X2(sa, sb, s01);
            UNPACK_F32X2(sc, sd, s23);
            unsigned long long p01, p23;
            PACK_F32X2(p01, fast_ex2(sa), fast_ex2(sb));
            PACK_F32X2(p23, fast_ex2(sc), poly_ex2(sd));   // 1 of 4 off MUFU
            ADD_F32X2_ACC(l2a, p01);
            ADD_F32X2_ACC(l2b, p23);
            FMA_F32X2_ACC(a2a, p01, vv.x);
            FMA_F32X2_ACC(a2b, p23, vv.y);
        }
        float lax, lay, lbx, lby, aax, aay, abx, aby;
        UNPACK_F32X2(lax, lay, l2a);
        UNPACK_F32X2(lbx, lby, l2b);
        UNPACK_F32X2(aax, aay, a2a);
        UNPACK_F32X2(abx, aby, a2b);
        float l = (lax + lay) + (lbx + lby);
        float acc = (aax + aay) + (abx + aby);
        for (int j = n4 * 4; j <= i; j++) {   // 0-3 tail elements
            const float pe = fast_ex2(qr * ks[j]);
            l += pe;
            acc += pe * vs[j];
        }
        const float o = acc / l;
        const __nv_bfloat16 hb = __float2bfloat16(o);
        g_aohi[c * TT + i] = hb;
        g_aolo[c * TT + i] = __float2bfloat16(o - __bfloat162float(hb));
    }
}

// ---------------------------------------------------------------------------
extern "C" void kernel_launch(void* const* d_in, const int* in_sizes, int n_in,
                              void* d_out, int out_size) {
    const float* x  = (const float*)d_in[0];
    const float* Wq = (const float*)d_in[1];
    const float* Wk = (const float*)d_in[2];
    const float* Wv = (const float*)d_in[3];
    const float* Wo = (const float*)d_in[4];
    float* y = (float*)d_out;

    cudaFuncSetAttribute(gemm1_kernel,
                         cudaFuncAttributeMaxDynamicSharedMemorySize, GEMM1_SMEM);
    cudaFuncSetAttribute(gemm2_kernel,
                         cudaFuncAttributeMaxDynamicSharedMemorySize, GEMM2_SMEM);

    split_kernel<<<1280, 256>>>((const float4*)x, (const float4*)Wq,
                                (const float4*)Wk, (const float4*)Wv,
                                (const float4*)Wo);
    gemm1_kernel<<<dim3(24, 8, 2), 256, GEMM1_SMEM>>>();
    attn_kernel<<<512, 256>>>(y);
    gemm2_kernel<<<dim3(16, 8, 2), 256, GEMM2_SMEM>>>(y);
}

// round 17
// speedup vs baseline: 1.1894x; 1.1894x over previous
#include <cuda_runtime.h>
#include <cuda_bf16.h>
#include <math.h>
#include <stdint.h>

#define TT 512
#define DD 512
#define LOG2E 1.4426950408889634f

// ---------------------------------------------------------------------------
// Device-global scratch
// ---------------------------------------------------------------------------
__device__ float g_qp[2][1536 * 512];                    // gemm1 split-K partials
__device__ __align__(16) __nv_bfloat16 g_aohi[DD * TT];  // ao hi, [d][t]
__device__ __align__(16) __nv_bfloat16 g_aolo[DD * TT];  // ao lo residual
__device__ __align__(16) __nv_bfloat16 gAhi[1536 * 512]; // Wq,Wk,Wv stacked hi
__device__ __align__(16) __nv_bfloat16 gAlo[1536 * 512];
__device__ __align__(16) __nv_bfloat16 gBhi[512 * 512];  // x [t][k]
__device__ __align__(16) __nv_bfloat16 gBlo[512 * 512];
__device__ __align__(16) __nv_bfloat16 gWohi[512 * 512]; // Wo [o][d]
__device__ __align__(16) __nv_bfloat16 gWolo[512 * 512];

__device__ __forceinline__ uint32_t smem_u32(const void* p) {
    uint32_t a;
    asm("{ .reg .u64 t; cvta.to.shared.u64 t, %1; cvt.u32.u64 %0, t; }"
        : "=r"(a) : "l"(p));
    return a;
}
__device__ __forceinline__ void cp16(uint32_t dst, const void* src) {
    asm volatile("cp.async.ca.shared.global [%0], [%1], 16;"
                 :: "r"(dst), "l"(src) : "memory");
}
__device__ __forceinline__ float fast_ex2(float x) {
    float r;
    asm("ex2.approx.ftz.f32 %0, %1;" : "=f"(r) : "f"(x));
    return r;
}

// Blackwell packed f32x2 ops (PTX sm_100+ family, baseline)
#define MUL_F32X2(d, a, b) \
    asm("mul.rn.f32x2 %0, %1, %2;" : "=l"(d) : "l"(a), "l"(b))
#define ADD_F32X2_ACC(d, a) \
    asm("add.rn.f32x2 %0, %0, %1;" : "+l"(d) : "l"(a))
#define FMA_F32X2_ACC(d, a, b) \
    asm("fma.rn.f32x2 %0, %1, %2, %0;" : "+l"(d) : "l"(a), "l"(b))
#define PACK_F32X2(d, lo, hi) \
    asm("mov.b64 %0, {%1, %2};" : "=l"(d) : "f"(lo), "f"(hi))
#define UNPACK_F32X2(lo, hi, s) \
    asm("mov.b64 {%0, %1}, %2;" : "=f"(lo), "=f"(hi) : "l"(s))

#define MMA16816(c, a, b) \
    asm volatile( \
        "mma.sync.aligned.m16n8k16.row.col.f32.bf16.bf16.f32 " \
        "{%0,%1,%2,%3},{%4,%5,%6,%7},{%8,%9},{%0,%1,%2,%3};" \
        : "+f"((c)[0]), "+f"((c)[1]), "+f"((c)[2]), "+f"((c)[3]) \
        : "r"((a)[0]), "r"((a)[1]), "r"((a)[2]), "r"((a)[3]), \
          "r"((b)[0]), "r"((b)[1]))

#define LDMX4(r, a) \
    asm volatile( \
        "ldmatrix.sync.aligned.m8n8.x4.shared.b16 {%0,%1,%2,%3}, [%4];" \
        : "=r"((r)[0]), "=r"((r)[1]), "=r"((r)[2]), "=r"((r)[3]) : "r"(a))

#define LDMX4T(r, a) \
    asm volatile( \
        "ldmatrix.sync.aligned.m8n8.x4.trans.shared.b16 {%0,%1,%2,%3}, [%4];" \
        : "=r"((r)[0]), "=r"((r)[1]), "=r"((r)[2]), "=r"((r)[3]) : "r"(a))

// ---------------------------------------------------------------------------
// Split kernel: fp32 -> bf16 hi + bf16 lo(residual). (unchanged)
// ---------------------------------------------------------------------------
__global__ void __launch_bounds__(256) split_kernel(
        const float4* __restrict__ x,  const float4* __restrict__ Wq,
        const float4* __restrict__ Wk, const float4* __restrict__ Wv,
        const float4* __restrict__ Wo) {
    const int gid = blockIdx.x * 256 + threadIdx.x;   // 0..327679
    const int seg = gid >> 16;
    const int off = gid & 65535;

    const float4* src;
    __nv_bfloat16 *dh, *dl;
    switch (seg) {
        case 0: src = Wq; dh = gAhi;          dl = gAlo;          break;
        case 1: src = Wk; dh = gAhi + 262144; dl = gAlo + 262144; break;
        case 2: src = Wv; dh = gAhi + 524288; dl = gAlo + 524288; break;
        case 3: src = x;  dh = gBhi;          dl = gBlo;          break;
        default: src = Wo; dh = gWohi;         dl = gWolo;         break;
    }
    float4 v = src[off];
    __nv_bfloat16 h0 = __float2bfloat16(v.x), h1 = __float2bfloat16(v.y);
    __nv_bfloat16 h2 = __float2bfloat16(v.z), h3 = __float2bfloat16(v.w);
    __nv_bfloat16 l0 = __float2bfloat16(v.x - __bfloat162float(h0));
    __nv_bfloat16 l1 = __float2bfloat16(v.y - __bfloat162float(h1));
    __nv_bfloat16 l2 = __float2bfloat16(v.z - __bfloat162float(h2));
    __nv_bfloat16 l3 = __float2bfloat16(v.w - __bfloat162float(h3));
    __nv_bfloat162* oh = (__nv_bfloat162*)dh;
    __nv_bfloat162* ol = (__nv_bfloat162*)dl;
    __nv_bfloat162 a, b;
    a.x = h0; a.y = h1; b.x = h2; b.y = h3;
    oh[off * 2] = a; oh[off * 2 + 1] = b;
    a.x = l0; a.y = l1; b.x = l2; b.y = l3;
    ol[off * 2] = a; ol[off * 2 + 1] = b;
}

// ---------------------------------------------------------------------------
// GEMM1 (round-13 config): 64x64 tile, split-K=2, 256 threads, 2-stage. PDL.
// ---------------------------------------------------------------------------
#define G1_MAT 9216                       // 64 rows * 144B
#define G1_CHUNK (4 * G1_MAT)             // 36864
#define GEMM1_SMEM (2 * G1_CHUNK)         // 73728
#define G2_CHUNK (2 * 5120 + 2 * 9216)    // 28672 (ATRANS A rows 80B)
#define GEMM2_SMEM (3 * G2_CHUNK)         // 86016 (3-stage, round-11 config)

__global__ void __launch_bounds__(256, 3) gemm1_kernel() {
    extern __shared__ char smem[];
    const uint32_t s0 = smem_u32(smem);
    const uint4* AH = (const uint4*)gAhi;
    const uint4* AL = (const uint4*)gAlo;
    const uint4* BH = (const uint4*)gBhi;
    const uint4* BL = (const uint4*)gBlo;

    const int tid = threadIdx.x;
    const int wid = tid >> 5, lane = tid & 31;
    const int g = lane >> 2, t4 = lane & 3;
    const int wm = (wid & 3) * 16;
    const int wn = (wid >> 2) * 32;
    const int m0 = blockIdx.x * 64, n0 = blockIdx.y * 64;
    const int kz = blockIdx.z;
    float* C = g_qp[kz];

    const int arow  = lane & 15;
    const int aksel = (lane >> 4) * 16;
    const int brow  = ((lane >> 4) & 1) * 8 + (lane & 7);
    const int bksel = ((lane >> 3) & 1) * 16;

    float accA[4][4] = {}, accB[4][4] = {};

    auto load_chunk = [&](int c, int st) {
        const uint32_t base = s0 + st * G1_CHUNK;
        const int kc = kz * 4 + c;
#pragma unroll
        for (int it = 0; it < 2; it++) {
            const int idx = it * 256 + tid;
            const int row = idx >> 3, c16 = idx & 7;
            const uint32_t so = row * 144 + c16 * 16;
            const size_t ga = (size_t)(m0 + row) * 64 + kc * 8 + c16;
            const size_t gb = (size_t)(n0 + row) * 64 + kc * 8 + c16;
            cp16(base + so,              AH + ga);
            cp16(base + G1_MAT + so,     AL + ga);
            cp16(base + 2 * G1_MAT + so, BH + gb);
            cp16(base + 3 * G1_MAT + so, BL + gb);
        }
        asm volatile("cp.async.commit_group;" ::: "memory");
    };

    // PDL: wait for split_kernel's bf16 operands to be visible.
    cudaGridDependencySynchronize();

    load_chunk(0, 0);

    for (int c = 0; c < 4; c++) {
        if (c < 3) {
            load_chunk(c + 1, (c + 1) & 1);
            asm volatile("cp.async.wait_group 1;" ::: "memory");
        } else {
            asm volatile("cp.async.wait_group 0;" ::: "memory");
        }
        __syncthreads();

        const uint32_t sb = s0 + (c & 1) * G1_CHUNK;
#pragma unroll
        for (int ks = 0; ks < 4; ks++) {
            const int kO = ks * 32;
            uint32_t ah[4], al[4], bh[2][4], bl[2][4];
            {
                const uint32_t ad = sb + (wm + arow) * 144 + kO + aksel;
                LDMX4(ah, ad);
                LDMX4(al, ad + G1_MAT);
            }
#pragma unroll
            for (int nb = 0; nb < 2; nb++) {
                const uint32_t bd = sb + 2 * G1_MAT
                                  + (wn + nb * 16 + brow) * 144 + kO + bksel;
                LDMX4(bh[nb], bd);
                LDMX4(bl[nb], bd + G1_MAT);
            }
#pragma unroll
            for (int nb = 0; nb < 2; nb++)
#pragma unroll
                for (int j = 0; j < 2; j++) {
                    MMA16816(accA[nb * 2 + j], ah, &bh[nb][j * 2]);
                    MMA16816(accB[nb * 2 + j], ah, &bl[nb][j * 2]);
                    MMA16816(accB[nb * 2 + j], al, &bh[nb][j * 2]);
                }
        }
        __syncthreads();
    }

    const int r = m0 + wm + g;
#pragma unroll
    for (int q = 0; q < 4; q++) {
        const int nb = q >> 1, j = q & 1;
        const int col = n0 + wn + nb * 16 + j * 8 + 2 * t4;
        *(float2*)&C[(size_t)r * 512 + col] =
            make_float2(accA[q][0] + accB[q][0], accA[q][1] + accB[q][1]);
        *(float2*)&C[(size_t)(r + 8) * 512 + col] =
            make_float2(accA[q][2] + accB[q][2], accA[q][3] + accB[q][3]);
    }
    cudaTriggerProgrammaticLaunchCompletion();
}

// ---------------------------------------------------------------------------
// GEMM2 (round-11 config, measured 9.06us): split-K=2, 3-stage, atomics. PDL.
// ---------------------------------------------------------------------------
__global__ void __launch_bounds__(256, 2) gemm2_kernel(float* __restrict__ y) {
    extern __shared__ char smem[];
    const uint32_t s0 = smem_u32(smem);
    const uint4* AH = (const uint4*)g_aohi;
    const uint4* AL = (const uint4*)g_aolo;
    const uint4* BH = (const uint4*)gWohi;
    const uint4* BL = (const uint4*)gWolo;

    constexpr int AROWB = 80, A_MAT = 64 * 80;
    constexpr int B_MAT = 9216;

    const int tid = threadIdx.x;
    const int wid = tid >> 5, lane = tid & 31;
    const int g = lane >> 2, t4 = lane & 3;
    const int wm = (wid & 1) * 16;
    const int wn = (wid >> 1) * 16;
    const int m0 = blockIdx.x * 32, n0 = blockIdx.y * 64;
    const int kc0 = blockIdx.z * 4;

    const int brow  = ((lane >> 4) & 1) * 8 + (lane & 7);
    const int bksel = ((lane >> 3) & 1) * 16;
    const int laneRow  = ((lane >> 4) & 1) * 8 + (lane & 7);
    const int laneMsel = ((lane >> 3) & 1) * 8;

    float accH[2][4] = {}, accM[2][4] = {}, accN[2][4] = {};

    auto load_chunk = [&](int kc, int st) {
        const uint32_t base = s0 + st * G2_CHUNK;
        {
            const int row = tid >> 2, c16 = tid & 3;
            const uint32_t so = row * AROWB + c16 * 16;
            const size_t ga = (size_t)(kc * 64 + row) * 64 + (m0 >> 3) + c16;
            cp16(base + so,         AH + ga);
            cp16(base + A_MAT + so, AL + ga);
        }
#pragma unroll
        for (int it = 0; it < 2; it++) {
            const int idx = it * 256 + tid;
            const int row = idx >> 3, c16 = idx & 7;
            const uint32_t so = row * 144 + c16 * 16;
            const size_t gb = (size_t)(n0 + row) * 64 + kc * 8 + c16;
            cp16(base + 2 * A_MAT + so,         BH + gb);
            cp16(base + 2 * A_MAT + B_MAT + so, BL + gb);
        }
        asm volatile("cp.async.commit_group;" ::: "memory");
    };

    // PDL: wait for attn_kernel's ao hi/lo and y-zeroing to be visible.
    cudaGridDependencySynchronize();

    load_chunk(kc0 + 0, 0);
    load_chunk(kc0 + 1, 1);

    for (int c = 0; c < 4; c++) {
        if (c + 2 < 4) {
            load_chunk(kc0 + c + 2, (c + 2) % 3);
            asm volatile("cp.async.wait_group 2;" ::: "memory");
        } else if (c + 1 < 4) {
            asm volatile("cp.async.wait_group 1;" ::: "memory");
        } else {
            asm volatile("cp.async.wait_group 0;" ::: "memory");
        }
        __syncthreads();

        const uint32_t sb = s0 + (c % 3) * G2_CHUNK;
#pragma unroll
        for (int ks = 0; ks < 4; ks++) {
            const int kO = ks * 32;
            uint32_t ah[4], al[4], bh[4], bl[4];
            {
                const uint32_t ad = sb + (ks * 16 + laneRow) * AROWB
                                  + (wm + laneMsel) * 2;
                LDMX4T(ah, ad);
                LDMX4T(al, ad + A_MAT);
            }
            {
                const uint32_t bd = sb + 2 * A_MAT + (wn + brow) * 144
                                  + kO + bksel;
                LDMX4(bh, bd);
                LDMX4(bl, bd + B_MAT);
            }
#pragma unroll
            for (int j = 0; j < 2; j++) {
                MMA16816(accH[j], ah, &bh[j * 2]);
                MMA16816(accM[j], ah, &bl[j * 2]);
                MMA16816(accN[j], al, &bh[j * 2]);
            }
        }
        __syncthreads();
    }

    const int r = m0 + wm + g;
#pragma unroll
    for (int j = 0; j < 2; j++) {
        const int col = n0 + wn + j * 8 + 2 * t4;
        atomicAdd(&y[(size_t)r * 512 + col],
                  accH[j][0] + accM[j][0] + accN[j][0]);
        atomicAdd(&y[(size_t)r * 512 + col + 1],
                  accH[j][1] + accM[j][1] + accN[j][1]);
        atomicAdd(&y[(size_t)(r + 8) * 512 + col],
                  accH[j][2] + accM[j][2] + accN[j][2]);
        atomicAdd(&y[(size_t)(r + 8) * 512 + col + 1],
                  accH[j][3] + accM[j][3] + accN[j][3]);
    }
}

// ---------------------------------------------------------------------------
// Attention (round-13 config): fused RoPE, 2-wide f32x2 loop, scalar f32 exp.
// Sums gemm1's split-K partials on load; zeroes y (pre-sync, independent). PDL.
// ---------------------------------------------------------------------------
__global__ void __launch_bounds__(256) attn_kernel(float* __restrict__ y) {
    const int c  = blockIdx.x;
    const int h  = c >> 6;
    const int ch = c & 63;
    const int fi = ch & 31;
    const int pc = ((h < 4) ? (h + 4) : (h - 4)) * 64 + ch;
    const float sgn = (h < 4) ? -1.0f : 1.0f;

    const float* q0  = g_qp[0] + (size_t)(0 * 512 + c)  * TT;
    const float* q1  = g_qp[1] + (size_t)(0 * 512 + c)  * TT;
    const float* qp0 = g_qp[0] + (size_t)(0 * 512 + pc) * TT;
    const float* qp1 = g_qp[1] + (size_t)(0 * 512 + pc) * TT;
    const float* k0  = g_qp[0] + (size_t)(1 * 512 + c)  * TT;
    const float* k1  = g_qp[1] + (size_t)(1 * 512 + c)  * TT;
    const float* kp0 = g_qp[0] + (size_t)(1 * 512 + pc) * TT;
    const float* kp1 = g_qp[1] + (size_t)(1 * 512 + pc) * TT;
    const float* v0  = g_qp[0] + (size_t)(2 * 512 + c)  * TT;
    const float* v1  = g_qp[1] + (size_t)(2 * 512 + c)  * TT;

    __shared__ __align__(8) float ks[512];   // rotated k, pre-scaled
    __shared__ __align__(8) float vs[512];
    __shared__ float cs[512];
    __shared__ float sn[512];
    __shared__ float s_invf;

    const int tid = threadIdx.x;
    // Independent of gemm1: zero y row c (for gemm2 atomics) before the sync.
    *(float2*)&y[c * 512 + tid * 2] = make_float2(0.f, 0.f);

    if (tid == 0) s_invf = (float)pow(10000.0, -(double)(2 * fi) / 64.0);

    // PDL: wait for gemm1's q/k/v partials.
    cudaGridDependencySynchronize();
    __syncthreads();
    const float invf = s_invf;

#pragma unroll
    for (int off = 0; off < 512; off += 256) {
        const int tt = tid + off;
        float sv, cv;
        sincosf((float)tt * invf, &sv, &cv);
        cs[tt] = cv;
        sn[tt] = sv;
        ks[tt] = ((k0[tt] + k1[tt]) * cv + sgn * (kp0[tt] + kp1[tt]) * sv)
               * (0.125f * LOG2E);
        vs[tt] = v0[tt] + v1[tt];
    }
    __syncthreads();

    const float2* k2 = (const float2*)ks;
    const unsigned long long* v2 = (const unsigned long long*)vs;

#pragma unroll
    for (int rep = 0; rep < 2; rep++) {
        const int i = rep ? (511 - tid) : tid;
        const float qr = (q0[i] + q1[i]) * cs[i]
                       + sgn * (qp0[i] + qp1[i]) * sn[i];
        unsigned long long qq;
        PACK_F32X2(qq, qr, qr);

        unsigned long long l2acc = 0ull;   // packed {0.f, 0.f}
        unsigned long long a2acc = 0ull;
        const int np = (i + 1) >> 1;
#pragma unroll 4
        for (int p = 0; p < np; p++) {
            const float2 kk = k2[p];               // LDS.64
            const unsigned long long vv = v2[p];   // LDS.64
            unsigned long long sp;
            MUL_F32X2(sp, qq, *(const unsigned long long*)&kk);
            float sa, sb2;
            UNPACK_F32X2(sa, sb2, sp);
            const float pa = fast_ex2(sa);
            const float pb = fast_ex2(sb2);
            unsigned long long pp;
            PACK_F32X2(pp, pa, pb);
            ADD_F32X2_ACC(l2acc, pp);
            FMA_F32X2_ACC(a2acc, pp, vv);
        }
        float lx, ly, ax, ay;
        UNPACK_F32X2(lx, ly, l2acc);
        UNPACK_F32X2(ax, ay, a2acc);
        float l = lx + ly, acc = ax + ay;
        if (!(i & 1)) {  // tail element j = i (even i)
            const float pe = fast_ex2(qr * ks[i]);
            l += pe;
            acc += pe * vs[i];
        }
        const float o = acc / l;
        const __nv_bfloat16 hb = __float2bfloat16(o);
        g_aohi[c * TT + i] = hb;
        g_aolo[c * TT + i] = __float2bfloat16(o - __bfloat162float(hb));
    }
    cudaTriggerProgrammaticLaunchCompletion();
}

// ---------------------------------------------------------------------------
extern "C" void kernel_launch(void* const* d_in, const int* in_sizes, int n_in,
                              void* d_out, int out_size) {
    const float* x  = (const float*)d_in[0];
    const float* Wq = (const float*)d_in[1];
    const float* Wk = (const float*)d_in[2];
    const float* Wv = (const float*)d_in[3];
    const float* Wo = (const float*)d_in[4];
    float* y = (float*)d_out;

    cudaFuncSetAttribute(gemm1_kernel,
                         cudaFuncAttributeMaxDynamicSharedMemorySize, GEMM1_SMEM);
    cudaFuncSetAttribute(gemm2_kernel,
                         cudaFuncAttributeMaxDynamicSharedMemorySize, GEMM2_SMEM);

    split_kernel<<<1280, 256>>>((const float4*)x, (const float4*)Wq,
                                (const float4*)Wk, (const float4*)Wv,
                                (const float4*)Wo);

    cudaLaunchAttribute pdl[1];
    pdl[0].id = cudaLaunchAttributeProgrammaticStreamSerialization;
    pdl[0].val.programmaticStreamSerializationAllowed = 1;

    {   // gemm1 (PDL after split)
        cudaLaunchConfig_t cfg = {};
        cfg.gridDim = dim3(24, 8, 2);
        cfg.blockDim = dim3(256, 1, 1);
        cfg.dynamicSmemBytes = GEMM1_SMEM;
        cfg.stream = 0;
        cfg.attrs = pdl;
        cfg.numAttrs = 1;
        cudaLaunchKernelEx(&cfg, gemm1_kernel);
    }
    {   // attn (PDL after gemm1)
        cudaLaunchConfig_t cfg = {};
        cfg.gridDim = dim3(512, 1, 1);
        cfg.blockDim = dim3(256, 1, 1);
        cfg.dynamicSmemBytes = 0;
        cfg.stream = 0;
        cfg.attrs = pdl;
        cfg.numAttrs = 1;
        cudaLaunchKernelEx(&cfg, attn_kernel, y);
    }
    {   // gemm2 (PDL after attn)
        cudaLaunchConfig_t cfg = {};
        cfg.gridDim = dim3(16, 8, 2);
        cfg.blockDim = dim3(256, 1, 1);
        cfg.dynamicSmemBytes = GEMM2_SMEM;
        cfg.stream = 0;
        cfg.attrs = pdl;
        cfg.numAttrs = 1;
        cudaLaunchKernelEx(&cfg, gemm2_kernel, y);
    }
}